// round 8
// baseline (speedup 1.0000x reference)
#include <cuda_runtime.h>
#include <math.h>

#define B 32
#define S 4096
#define H 1024
#define WARPS_PER_BLOCK 8
#define K1_THREADS (WARPS_PER_BLOCK * 32)      // 256
#define K1_BLOCKS 444                          // 3 blocks/SM on 148 SMs
#define NWARPS (K1_BLOCKS * WARPS_PER_BLOCK)   // 3552
#define WARPS_PER_BATCH (NWARPS / B)           // 111
#define ROWS_BASE (S / WARPS_PER_BATCH)        // 36
#define ROWS_REM (S % WARPS_PER_BATCH)         // 100 (first 100 warps do 37)

// Scratch (__device__ globals; no dynamic allocation allowed)
__device__ float4 g_ctx_partial[NWARPS * (H / 4)];   // 14.2 MB, batch-contiguous
__device__ float  g_m_partial[NWARPS];
__device__ float  g_l_partial[NWARPS];
__device__ float  g_M[B];
__device__ float  g_invL[B];

// ---------------------------------------------------------------------------
// Kernel 1: single streaming pass over keys, 3 blocks/SM.
// q lives in a per-warp SMEM slab (frees 32 regs -> 3 blocks/SM); keys are
// read ONCE into registers per row (the proven R5 structure).
// ---------------------------------------------------------------------------
__global__ __launch_bounds__(K1_THREADS, 3)
void k1_scores_partial_ctx(const float* __restrict__ query,
                           const float* __restrict__ keys,
                           float* __restrict__ out_weights /* raw scores */)
{
    __shared__ float s_q[WARPS_PER_BLOCK][H];   // 32 KB/block

    const int w    = threadIdx.x >> 5;
    const int lane = threadIdx.x & 31;
    const int wg   = blockIdx.x * WARPS_PER_BLOCK + w;
    const int b    = wg / WARPS_PER_BATCH;
    const int i    = wg % WARPS_PER_BATCH;
    const int start = i * ROWS_BASE + (i < ROWS_REM ? i : ROWS_REM);
    const int count = ROWS_BASE + (i < ROWS_REM ? 1 : 0);

    // stage this warp's q row into smem (coalesced float4)
    {
        const float4* qg = reinterpret_cast<const float4*>(query + (size_t)b * H);
        float4* qs = reinterpret_cast<float4*>(s_q[w]);
#pragma unroll
        for (int j = 0; j < 8; ++j) qs[lane + 32 * j] = qg[lane + 32 * j];
    }
    __syncwarp();
    const float4* qs = reinterpret_cast<const float4*>(s_q[w]);

    float4 acc[8];
#pragma unroll
    for (int j = 0; j < 8; ++j) acc[j] = make_float4(0.f, 0.f, 0.f, 0.f);
    float m = -INFINITY;
    float l = 0.f;

    const size_t base = ((size_t)b * S + start) * H;
    float* wout = out_weights + (size_t)b * S + start;

    for (int r = 0; r < count; ++r) {
        const float4* k4 = reinterpret_cast<const float4*>(keys + base + (size_t)r * H);
        float4 kv[8];
#pragma unroll
        for (int j = 0; j < 8; ++j) kv[j] = k4[lane + 32 * j];

        float d = 0.f;
#pragma unroll
        for (int j = 0; j < 8; ++j) {
            float4 qv = qs[lane + 32 * j];
            d = fmaf(qv.x, kv[j].x, d);
            d = fmaf(qv.y, kv[j].y, d);
            d = fmaf(qv.z, kv[j].z, d);
            d = fmaf(qv.w, kv[j].w, d);
        }
#pragma unroll
        for (int o = 16; o > 0; o >>= 1)
            d += __shfl_xor_sync(0xFFFFFFFFu, d, o);

        if (lane == 0) wout[r] = d;

        float p;
        if (d > m) {                       // warp-uniform branch
            float scale = __expf(m - d);   // first iter: exp(-inf)=0
#pragma unroll
            for (int j = 0; j < 8; ++j) {
                acc[j].x *= scale; acc[j].y *= scale;
                acc[j].z *= scale; acc[j].w *= scale;
            }
            l = fmaf(l, scale, 1.f);
            m = d;
            p = 1.f;
        } else {
            p = __expf(d - m);
            l += p;
        }
#pragma unroll
        for (int j = 0; j < 8; ++j) {
            acc[j].x = fmaf(p, kv[j].x, acc[j].x);
            acc[j].y = fmaf(p, kv[j].y, acc[j].y);
            acc[j].z = fmaf(p, kv[j].z, acc[j].z);
            acc[j].w = fmaf(p, kv[j].w, acc[j].w);
        }
    }

    float4* dst = &g_ctx_partial[(size_t)wg * (H / 4)];
#pragma unroll
    for (int j = 0; j < 8; ++j) dst[lane + 32 * j] = acc[j];
    if (lane == 0) {
        g_m_partial[wg] = m;
        g_l_partial[wg] = l;
    }
}

// ---------------------------------------------------------------------------
// Kernel 2a: one block (128 thr) per batch: M_b, 1/L_b from (m,l) pairs.
// Also zeroes out_ctx[b] (harness poisons d_out).
// ---------------------------------------------------------------------------
__global__ __launch_bounds__(128)
void k2a_stats(float* __restrict__ out_ctx)
{
    const int b = blockIdx.x;
    const int t = threadIdx.x;     // 0..127, slots 0..110 valid
    __shared__ float sm[4], sl[4], sM;

    float mc = -INFINITY, lc = 0.f;
    if (t < WARPS_PER_BATCH) {
        const int p = b * WARPS_PER_BATCH + t;
        mc = g_m_partial[p];
        lc = g_l_partial[p];
    }

    float4* oc = reinterpret_cast<float4*>(out_ctx + (size_t)b * H);
#pragma unroll
    for (int j = 0; j < 2; ++j)
        oc[t + 128 * j] = make_float4(0.f, 0.f, 0.f, 0.f);

    float v = mc;
#pragma unroll
    for (int o = 16; o > 0; o >>= 1)
        v = fmaxf(v, __shfl_xor_sync(0xFFFFFFFFu, v, o));
    if ((t & 31) == 0) sm[t >> 5] = v;
    __syncthreads();
    if (t == 0) sM = fmaxf(fmaxf(sm[0], sm[1]), fmaxf(sm[2], sm[3]));
    __syncthreads();
    const float M = sM;

    float s = lc * __expf(mc - M);   // idle slots contribute 0
#pragma unroll
    for (int o = 16; o > 0; o >>= 1)
        s += __shfl_xor_sync(0xFFFFFFFFu, s, o);
    if ((t & 31) == 0) sl[t >> 5] = s;
    __syncthreads();
    if (t == 0) {
        g_M[b] = M;
        g_invL[b] = 1.f / (sl[0] + sl[1] + sl[2] + sl[3]);
    }
}

// ---------------------------------------------------------------------------
// Kernel 2b: blocks 0..127 normalize weights (float4);
// blocks 128..383: (b,sub) combines a CONTIGUOUS run of 14 slots and
// atomicAdds the scaled context into out_ctx.
// ---------------------------------------------------------------------------
#define K2_THREADS 256
#define WNORM_BLOCKS ((B * S / 4) / K2_THREADS)   // 128
#define COMBINE_SPLIT 8
#define SLOTS_PER_CBLOCK 14                       // 8*14=112 >= 111

__global__ __launch_bounds__(K2_THREADS)
void k2b_finalize(float* __restrict__ out_ctx, float* __restrict__ out_weights)
{
    if (blockIdx.x < WNORM_BLOCKS) {
        const int idx = blockIdx.x * K2_THREADS + threadIdx.x;  // float4 idx
        const int b = idx / (S / 4);
        const float M = g_M[b], invL = g_invL[b];
        float4 s = reinterpret_cast<float4*>(out_weights)[idx];
        s.x = __expf(s.x - M) * invL;
        s.y = __expf(s.y - M) * invL;
        s.z = __expf(s.z - M) * invL;
        s.w = __expf(s.w - M) * invL;
        reinterpret_cast<float4*>(out_weights)[idx] = s;
    } else {
        const int g   = blockIdx.x - WNORM_BLOCKS;   // 0..255
        const int b   = g >> 3;
        const int sub = g & (COMBINE_SPLIT - 1);
        const float M = g_M[b], invL = g_invL[b];
        const int t = threadIdx.x;                   // float4 element t of 256
        const int i0 = sub * SLOTS_PER_CBLOCK;
        const int i1 = (i0 + SLOTS_PER_CBLOCK < WARPS_PER_BATCH)
                         ? i0 + SLOTS_PER_CBLOCK : WARPS_PER_BATCH;
        float4 c = make_float4(0.f, 0.f, 0.f, 0.f);
        for (int i = i0; i < i1; ++i) {
            const int p = b * WARPS_PER_BATCH + i;
            const float f = __expf(g_m_partial[p] - M) * invL;
            float4 v = g_ctx_partial[(size_t)p * (H / 4) + t];
            c.x = fmaf(f, v.x, c.x);
            c.y = fmaf(f, v.y, c.y);
            c.z = fmaf(f, v.z, c.z);
            c.w = fmaf(f, v.w, c.w);
        }
        float* o = out_ctx + (size_t)b * H + 4 * t;
        atomicAdd(o + 0, c.x);
        atomicAdd(o + 1, c.y);
        atomicAdd(o + 2, c.z);
        atomicAdd(o + 3, c.w);
    }
}

extern "C" void kernel_launch(void* const* d_in, const int* in_sizes, int n_in,
                              void* d_out, int out_size)
{
    const float* query = (const float*)d_in[0];   // (32,1,1024)
    const float* keys  = (const float*)d_in[1];   // (32,4096,1024)
    float* out = (float*)d_out;
    float* out_ctx = out;                  // (B,H)
    float* out_w   = out + (size_t)B * H;  // (B,S)

    k1_scores_partial_ctx<<<K1_BLOCKS, K1_THREADS>>>(query, keys, out_w);
    k2a_stats<<<B, 128>>>(out_ctx);
    k2b_finalize<<<WNORM_BLOCKS + B * COMBINE_SPLIT, K2_THREADS>>>(out_ctx, out_w);
}

// round 9
// speedup vs baseline: 1.7076x; 1.7076x over previous
#include <cuda_runtime.h>
#include <math.h>

#define B 32
#define S 4096
#define H 1024
#define WARPS_PER_BLOCK 8
#define K1_THREADS (WARPS_PER_BLOCK * 32)      // 256
#define K1_BLOCKS 296                          // 2 blocks/SM on 148 SMs
#define NWARPS (K1_BLOCKS * WARPS_PER_BLOCK)   // 2368
#define WARPS_PER_BATCH (NWARPS / B)           // 74
#define ROWS_BASE (S / WARPS_PER_BATCH)        // 55
#define ROWS_REM (S % WARPS_PER_BATCH)         // 26 (first 26 warps do 56 rows)

// Scratch (__device__ globals; no dynamic allocation allowed)
__device__ float4 g_ctx_partial[NWARPS * (H / 4)];   // 9.5 MB, batch-contiguous
__device__ float  g_m_partial[NWARPS];
__device__ float  g_l_partial[NWARPS];
__device__ float  g_M[B];
__device__ float  g_invL[B];

// ---------------------------------------------------------------------------
// Kernel 1: single streaming pass over keys (the proven 82.6us R5 kernel),
// with batch-contiguous warp mapping: b = wg / 74, slot i = wg % 74.
// q, kv, acc all in registers; 2 blocks/SM; 16 warps/SM.
// ---------------------------------------------------------------------------
__global__ __launch_bounds__(K1_THREADS)
void k1_scores_partial_ctx(const float* __restrict__ query,
                           const float* __restrict__ keys,
                           float* __restrict__ out_weights /* raw scores */)
{
    const int wg   = blockIdx.x * WARPS_PER_BLOCK + (threadIdx.x >> 5);
    const int lane = threadIdx.x & 31;
    const int b    = wg / WARPS_PER_BATCH;
    const int i    = wg % WARPS_PER_BATCH;
    const int start = i * ROWS_BASE + (i < ROWS_REM ? i : ROWS_REM);
    const int count = ROWS_BASE + (i < ROWS_REM ? 1 : 0);

    const float4* q4 = reinterpret_cast<const float4*>(query + (size_t)b * H);
    float4 qv[8];
#pragma unroll
    for (int j = 0; j < 8; ++j) qv[j] = q4[lane + 32 * j];

    float4 acc[8];
#pragma unroll
    for (int j = 0; j < 8; ++j) acc[j] = make_float4(0.f, 0.f, 0.f, 0.f);
    float m = -INFINITY;
    float l = 0.f;

    const size_t base = ((size_t)b * S + start) * H;
    float* wout = out_weights + (size_t)b * S + start;

    for (int r = 0; r < count; ++r) {
        const float4* k4 = reinterpret_cast<const float4*>(keys + base + (size_t)r * H);
        float4 kv[8];
#pragma unroll
        for (int j = 0; j < 8; ++j) kv[j] = k4[lane + 32 * j];

        float d = 0.f;
#pragma unroll
        for (int j = 0; j < 8; ++j) {
            d = fmaf(qv[j].x, kv[j].x, d);
            d = fmaf(qv[j].y, kv[j].y, d);
            d = fmaf(qv[j].z, kv[j].z, d);
            d = fmaf(qv[j].w, kv[j].w, d);
        }
#pragma unroll
        for (int o = 16; o > 0; o >>= 1)
            d += __shfl_xor_sync(0xFFFFFFFFu, d, o);

        if (lane == 0) wout[r] = d;

        float p;
        if (d > m) {                       // warp-uniform branch
            float scale = __expf(m - d);   // first iter: exp(-inf)=0
#pragma unroll
            for (int j = 0; j < 8; ++j) {
                acc[j].x *= scale; acc[j].y *= scale;
                acc[j].z *= scale; acc[j].w *= scale;
            }
            l = fmaf(l, scale, 1.f);
            m = d;
            p = 1.f;
        } else {
            p = __expf(d - m);
            l += p;
        }
#pragma unroll
        for (int j = 0; j < 8; ++j) {
            acc[j].x = fmaf(p, kv[j].x, acc[j].x);
            acc[j].y = fmaf(p, kv[j].y, acc[j].y);
            acc[j].z = fmaf(p, kv[j].z, acc[j].z);
            acc[j].w = fmaf(p, kv[j].w, acc[j].w);
        }
    }

    float4* dst = &g_ctx_partial[(size_t)wg * (H / 4)];
#pragma unroll
    for (int j = 0; j < 8; ++j) dst[lane + 32 * j] = acc[j];
    if (lane == 0) {
        g_m_partial[wg] = m;
        g_l_partial[wg] = l;
    }
}

// ---------------------------------------------------------------------------
// Kernel 2a: one block (128 thr) per batch: M_b, 1/L_b from contiguous (m,l).
// Also zeroes out_ctx[b] (harness poisons d_out).
// ---------------------------------------------------------------------------
__global__ __launch_bounds__(128)
void k2a_stats(float* __restrict__ out_ctx)
{
    const int b = blockIdx.x;
    const int t = threadIdx.x;     // 0..127, slots 0..73 valid
    __shared__ float sm[4], sl[4], sM;

    float mc = -INFINITY, lc = 0.f;
    if (t < WARPS_PER_BATCH) {
        const int p = b * WARPS_PER_BATCH + t;
        mc = g_m_partial[p];
        lc = g_l_partial[p];
    }

    float4* oc = reinterpret_cast<float4*>(out_ctx + (size_t)b * H);
#pragma unroll
    for (int j = 0; j < 2; ++j)
        oc[t + 128 * j] = make_float4(0.f, 0.f, 0.f, 0.f);

    float v = mc;
#pragma unroll
    for (int o = 16; o > 0; o >>= 1)
        v = fmaxf(v, __shfl_xor_sync(0xFFFFFFFFu, v, o));
    if ((t & 31) == 0) sm[t >> 5] = v;
    __syncthreads();
    if (t == 0) sM = fmaxf(fmaxf(sm[0], sm[1]), fmaxf(sm[2], sm[3]));
    __syncthreads();
    const float M = sM;

    float s = lc * __expf(mc - M);   // idle slots contribute 0
#pragma unroll
    for (int o = 16; o > 0; o >>= 1)
        s += __shfl_xor_sync(0xFFFFFFFFu, s, o);
    if ((t & 31) == 0) sl[t >> 5] = s;
    __syncthreads();
    if (t == 0) {
        g_M[b] = M;
        g_invL[b] = 1.f / (sl[0] + sl[1] + sl[2] + sl[3]);
    }
}

// ---------------------------------------------------------------------------
// Kernel 2b: blocks 0..127 normalize weights (float4);
// blocks 128..383: (b,sub) combines a CONTIGUOUS run of 10 slots and
// atomicAdds the scaled context into out_ctx.
// ---------------------------------------------------------------------------
#define K2_THREADS 256
#define WNORM_BLOCKS ((B * S / 4) / K2_THREADS)   // 128
#define COMBINE_SPLIT 8
#define SLOTS_PER_CBLOCK 10                       // 8*10=80 >= 74

__global__ __launch_bounds__(K2_THREADS)
void k2b_finalize(float* __restrict__ out_ctx, float* __restrict__ out_weights)
{
    if (blockIdx.x < WNORM_BLOCKS) {
        const int idx = blockIdx.x * K2_THREADS + threadIdx.x;  // float4 idx
        const int b = idx / (S / 4);
        const float M = g_M[b], invL = g_invL[b];
        float4 s = reinterpret_cast<float4*>(out_weights)[idx];
        s.x = __expf(s.x - M) * invL;
        s.y = __expf(s.y - M) * invL;
        s.z = __expf(s.z - M) * invL;
        s.w = __expf(s.w - M) * invL;
        reinterpret_cast<float4*>(out_weights)[idx] = s;
    } else {
        const int g   = blockIdx.x - WNORM_BLOCKS;   // 0..255
        const int b   = g >> 3;
        const int sub = g & (COMBINE_SPLIT - 1);
        const float M = g_M[b], invL = g_invL[b];
        const int t = threadIdx.x;                   // float4 element t of 256
        const int i0 = sub * SLOTS_PER_CBLOCK;
        const int i1 = (i0 + SLOTS_PER_CBLOCK < WARPS_PER_BATCH)
                         ? i0 + SLOTS_PER_CBLOCK : WARPS_PER_BATCH;
        float4 c = make_float4(0.f, 0.f, 0.f, 0.f);
        for (int i = i0; i < i1; ++i) {
            const int p = b * WARPS_PER_BATCH + i;
            const float f = __expf(g_m_partial[p] - M) * invL;
            float4 v = g_ctx_partial[(size_t)p * (H / 4) + t];
            c.x = fmaf(f, v.x, c.x);
            c.y = fmaf(f, v.y, c.y);
            c.z = fmaf(f, v.z, c.z);
            c.w = fmaf(f, v.w, c.w);
        }
        if (i0 < WARPS_PER_BATCH) {
            float* o = out_ctx + (size_t)b * H + 4 * t;
            atomicAdd(o + 0, c.x);
            atomicAdd(o + 1, c.y);
            atomicAdd(o + 2, c.z);
            atomicAdd(o + 3, c.w);
        }
    }
}

extern "C" void kernel_launch(void* const* d_in, const int* in_sizes, int n_in,
                              void* d_out, int out_size)
{
    const float* query = (const float*)d_in[0];   // (32,1,1024)
    const float* keys  = (const float*)d_in[1];   // (32,4096,1024)
    float* out = (float*)d_out;
    float* out_ctx = out;                  // (B,H)
    float* out_w   = out + (size_t)B * H;  // (B,S)

    k1_scores_partial_ctx<<<K1_BLOCKS, K1_THREADS>>>(query, keys, out_w);
    k2a_stats<<<B, 128>>>(out_ctx);
    k2b_finalize<<<WNORM_BLOCKS + B * COMBINE_SPLIT, K2_THREADS>>>(out_ctx, out_w);
}